// round 8
// baseline (speedup 1.0000x reference)
#include <cuda_runtime.h>
#include <cuda_bf16.h>

// OneHotEncoder: per-row token histogram, tokens [256, 2048] i32 -> counts [256, 32000] f32,
// pad_idx=0 skipped. `lengths` input is dead in the reference.
//
// R4 strategy: split the two independent phases.
//   1) cudaMemsetAsync zeroes the whole 32.77 MB output — the driver memset
//      path is the fastest pure store stream (graph-capturable memset node,
//      no allocation). This avoids the 256-CTA bursty STG pattern + L1tex
//      store-queue overflow that bound R3.
//   2) A tiny scatter kernel: each thread loads 4 tokens (LDG.128) and issues
//      up to 4 fire-and-forget RED.ADD.F32 global atomics. No zero/atomic
//      same-line interference inside one kernel, no barriers, no smem.
// The memset->scatter dependency is the stream order inside the graph.

#define VOCAB   32000
#define SEQ_T   2048
#define THREADS 1024
#define TOK_PER_THREAD 4

__global__ __launch_bounds__(THREADS)
void onehot_scatter_kernel(const int* __restrict__ tokens,
                           float* __restrict__ out)
{
    // Flat index over all B*T tokens, 4 per thread (4 divides 2048, so all
    // four tokens of an int4 belong to the same row).
    const int g = blockIdx.x * THREADS + threadIdx.x;     // int4 index
    const int4 t = reinterpret_cast<const int4*>(tokens)[g];

    const int row = (g * TOK_PER_THREAD) / SEQ_T;
    float* row_out = out + (size_t)row * VOCAB;

    if (t.x != 0) atomicAdd(row_out + t.x, 1.0f);   // RED.ADD.F32, no return
    if (t.y != 0) atomicAdd(row_out + t.y, 1.0f);
    if (t.z != 0) atomicAdd(row_out + t.z, 1.0f);
    if (t.w != 0) atomicAdd(row_out + t.w, 1.0f);
}

extern "C" void kernel_launch(void* const* d_in, const int* in_sizes, int n_in,
                              void* d_out, int out_size)
{
    const int* tokens = (const int*)d_in[0];   // [256, 2048] int32
    // d_in[1] = lengths, unused by the reference computation.
    float* out = (float*)d_out;                // [256, 32000] f32

    const int n_tokens = in_sizes[0];                          // 256*2048 = 524288
    const int n_thread = n_tokens / TOK_PER_THREAD;            // 131072
    const int grid     = n_thread / THREADS;                   // 128

    // Phase 1: zero the output (graph-capturable memset node).
    cudaMemsetAsync(d_out, 0, (size_t)out_size * sizeof(float));

    // Phase 2: scatter-add the non-pad tokens.
    onehot_scatter_kernel<<<grid, THREADS>>>(tokens, out);
}

// round 9
// speedup vs baseline: 1.1662x; 1.1662x over previous
#include <cuda_runtime.h>
#include <cuda_bf16.h>

// OneHotEncoder: per-row token histogram, tokens [256, 2048] i32 -> counts [256, 32000] f32,
// pad_idx=0 skipped. `lengths` is dead in the reference.
//
// R5: vocab-sliced shared-memory histogram.
//  - Grid (256 rows x 4 vocab slices), 256 threads/CTA, 16 KB smem each.
//    ~7 CTAs/SM -> one wave with far more latency overlap than R2's 2 CTAs/SM.
//  - Each CTA reads its whole row (512 int4, L2-broadcast across the row's 4
//    slice-CTAs) and bins only tokens inside its 8000-wide vocab slice into a
//    packed 2xu16-per-u32 smem histogram (max count 2048 < 65536: no carry).
//  - Epilogue unpacks to float4 STG.128. Output written exactly once, never
//    read -> stays L2-resident at replay steady state, DRAM idle (the lesson
//    from R4's memset+scatter split, which paid 23 MB of DRAM atomic misses).

#define VOCAB    32000
#define SEQ_T    2048
#define NSPLIT   4
#define VSLICE   (VOCAB / NSPLIT)          // 8000 vocab entries per slice
#define NWORDS   (VSLICE / 2)              // 4000 packed u32 words
#define THREADS  256

__global__ __launch_bounds__(THREADS, 8)
void onehot_slice_kernel(const int* __restrict__ tokens,
                         float* __restrict__ out)
{
    __shared__ unsigned int hist[NWORDS];  // 16 KB: 8000 u16 counters

    const int row   = blockIdx.x;
    const int vbase = blockIdx.y * VSLICE;
    const int tid   = threadIdx.x;

    // --- zero: 1000 uint4 / 256 threads -> 4 STS.128 each ---
    uint4* h4 = reinterpret_cast<uint4*>(hist);
    #pragma unroll
    for (int i = tid; i < NWORDS / 4; i += THREADS) {
        h4[i] = make_uint4(0u, 0u, 0u, 0u);
    }
    __syncthreads();

    // --- bin in-slice tokens: 512 int4 / 256 threads -> 2 LDG.128 each ---
    const int4* tok4 = reinterpret_cast<const int4*>(tokens + (size_t)row * SEQ_T);
    #pragma unroll
    for (int i = tid; i < SEQ_T / 4; i += THREADS) {
        int4 t = tok4[i];
        // pad (0) must be skipped explicitly for slice 0; for other slices the
        // unsigned range check rejects it via underflow.
        unsigned vx = (unsigned)(t.x - vbase);
        unsigned vy = (unsigned)(t.y - vbase);
        unsigned vz = (unsigned)(t.z - vbase);
        unsigned vw = (unsigned)(t.w - vbase);
        if (t.x != 0 && vx < VSLICE) atomicAdd(&hist[vx >> 1], 1u << ((vx & 1u) << 4));
        if (t.y != 0 && vy < VSLICE) atomicAdd(&hist[vy >> 1], 1u << ((vy & 1u) << 4));
        if (t.z != 0 && vz < VSLICE) atomicAdd(&hist[vz >> 1], 1u << ((vz & 1u) << 4));
        if (t.w != 0 && vw < VSLICE) atomicAdd(&hist[vw >> 1], 1u << ((vw & 1u) << 4));
    }
    __syncthreads();

    // --- dump: 2000 float4 / 256 threads -> 8 x (LDS.64 + 4 cvt + STG.128) ---
    float4* out4 = reinterpret_cast<float4*>(out + (size_t)row * VOCAB + vbase);
    const uint2* h2 = reinterpret_cast<const uint2*>(hist);
    #pragma unroll
    for (int i = tid; i < NWORDS / 2; i += THREADS) {
        uint2 w = h2[i];
        float4 v;
        v.x = (float)(w.x & 0xFFFFu);
        v.y = (float)(w.x >> 16);
        v.z = (float)(w.y & 0xFFFFu);
        v.w = (float)(w.y >> 16);
        out4[i] = v;
    }
}

extern "C" void kernel_launch(void* const* d_in, const int* in_sizes, int n_in,
                              void* d_out, int out_size)
{
    const int* tokens = (const int*)d_in[0];   // [256, 2048] int32
    // d_in[1] = lengths, unused by the reference computation.
    float* out = (float*)d_out;                // [256, 32000] f32

    const int batch = in_sizes[0] / SEQ_T;     // 256

    dim3 grid(batch, NSPLIT);
    onehot_slice_kernel<<<grid, THREADS>>>(tokens, out);
}